// round 7
// baseline (speedup 1.0000x reference)
#include <cuda_runtime.h>
#include <cstdint>

#define NN 100000
#define F1 128
#define FH 64
#define FO 32
#define EMAX 1600000
#define NSCAN_BLK 196            // ceil(100000/512)

// Scratch (no allocations allowed).
__device__ int   g_deg[NN];
__device__ int   g_cur[NN];
__device__ int   g_off[NN];
__device__ int   g_scan[NN];
__device__ int   g_bsum[NSCAN_BLK];
__device__ int   g_bsumx[NSCAN_BLK];
__device__ float g_dinv[NN];
__device__ int2  g_edge[EMAX];            // (src, norm) grouped by dst
__device__ float g_h1[(size_t)NN * FH];   // x @ W1
__device__ float g_a1[(size_t)NN * FH];   // layer-1 activations (post ReLU)
__device__ float g_h3[(size_t)NN * FO];   // a1 @ W2

#define FMA2(acc, aa, ww) \
    asm("fma.rn.f32x2 %0, %1, %2, %0;" : "+l"(acc) : "l"(aa), "l"(ww))
#define BCAST2(aa, a) \
    asm("mov.b64 %0, {%1, %1};" : "=l"(aa) : "f"(a))

// ---------------------------------------------------------------------------
__global__ void k_init() {
    int i = blockIdx.x * blockDim.x + threadIdx.x;
    if (i < NN) g_deg[i] = 0;
}

__global__ void k_deg(const int* __restrict__ ei, int E) {
    int i = blockIdx.x * blockDim.x + threadIdx.x;
    if (i < E) atomicAdd(&g_deg[ei[E + i]], 1);
}

// ---- exclusive prefix sum of g_deg -> g_off --------------------------------
__global__ __launch_bounds__(512) void k_scan1() {
    __shared__ int sh[512];
    int t = threadIdx.x;
    int i = blockIdx.x * 512 + t;
    int v = (i < NN) ? g_deg[i] : 0;
    sh[t] = v;
    for (int d = 1; d < 512; d <<= 1) {
        __syncthreads();
        int u = (t >= d) ? sh[t - d] : 0;
        __syncthreads();
        sh[t] += u;
    }
    __syncthreads();
    if (i < NN) g_scan[i] = sh[t];
    if (t == 511) g_bsum[blockIdx.x] = sh[511];
}

__global__ __launch_bounds__(256) void k_scan2() {
    __shared__ int sh[256];
    int t = threadIdx.x;
    int v = (t < NSCAN_BLK) ? g_bsum[t] : 0;
    sh[t] = v;
    for (int d = 1; d < 256; d <<= 1) {
        __syncthreads();
        int u = (t >= d) ? sh[t - d] : 0;
        __syncthreads();
        sh[t] += u;
    }
    __syncthreads();
    if (t < NSCAN_BLK) g_bsumx[t] = sh[t] - v;   // exclusive
}

// offsets + cursor reset + dinv (fused)
__global__ void k_scan3() {
    int i = blockIdx.x * blockDim.x + threadIdx.x;
    if (i >= NN) return;
    int deg = g_deg[i];
    g_off[i] = g_scan[i] - deg + g_bsumx[i >> 9];  // exclusive offset
    g_cur[i] = 0;
    g_dinv[i] = rsqrtf((float)deg + 1.0f);         // +1 self-loop
}

// Scatter edges into destination-grouped order, packing (src, norm).
__global__ void k_scatter(const int* __restrict__ ei, int E) {
    int e = blockIdx.x * blockDim.x + threadIdx.x;
    if (e >= E) return;
    int s = ei[e];
    int d = ei[E + e];
    float norm = g_dinv[s] * g_dinv[d];
    int pos = g_off[d] + atomicAdd(&g_cur[d], 1);
    g_edge[pos] = make_int2(s, __float_as_int(norm));
}

// ---------------------------------------------------------------------------
// GEMM1: h1[NN,64] = x[NN,128] @ W1[128,64].
// 64 rows/block, 128 threads, 4 rows x 8 cols per thread, f32x2 FMA.
__global__ __launch_bounds__(128) void k_gemm1(const float* __restrict__ x,
                                               const float* __restrict__ W) {
    __shared__ float Ws[F1 * FH];   // 32 KB [k][col]
    __shared__ float xs[64 * F1];   // 32 KB [r][k]
    int tid = threadIdx.x;
    float4* Ws4 = (float4*)Ws;
    const float4* W4 = (const float4*)W;
    for (int i = tid; i < F1 * FH / 4; i += 128) Ws4[i] = W4[i];
    int row0 = blockIdx.x * 64;
    float4* xs4 = (float4*)xs;
    const float4* x4 = (const float4*)x;
    for (int i = tid; i < 64 * F1 / 4; i += 128) {
        int row = row0 + (i >> 5);                 // 32 float4 per row
        xs4[i] = (row < NN) ? x4[(size_t)row * 32 + (i & 31)]
                            : make_float4(0.f, 0.f, 0.f, 0.f);
    }
    __syncthreads();

    int tx = tid & 7;               // cols 8tx..8tx+7
    int ty = tid >> 3;              // rows 4ty..4ty+3
    const float* xr = xs + 4 * ty * F1;
    const ulonglong2* Wp = (const ulonglong2*)Ws;  // 16 ulonglong2 per k-row
    unsigned long long acc[4][4] = {};             // 0 bits == {0.f,0.f}
    #pragma unroll 8
    for (int k = 0; k < F1; k++) {
        ulonglong2 w01 = Wp[k * 16 + 2 * tx];      // cols 8tx..8tx+3
        ulonglong2 w23 = Wp[k * 16 + 2 * tx + 1];  // cols 8tx+4..8tx+7
        #pragma unroll
        for (int j = 0; j < 4; j++) {
            float a = xr[j * F1 + k];
            unsigned long long aa;
            BCAST2(aa, a);
            FMA2(acc[j][0], aa, w01.x);
            FMA2(acc[j][1], aa, w01.y);
            FMA2(acc[j][2], aa, w23.x);
            FMA2(acc[j][3], aa, w23.y);
        }
    }
    ulonglong2* h1v = (ulonglong2*)g_h1;           // 16 ulonglong2 per row
    #pragma unroll
    for (int j = 0; j < 4; j++) {
        int row = row0 + 4 * ty + j;
        if (row < NN) {
            h1v[(size_t)row * 16 + 2 * tx]     = make_ulonglong2(acc[j][0], acc[j][1]);
            h1v[(size_t)row * 16 + 2 * tx + 1] = make_ulonglong2(acc[j][2], acc[j][3]);
        }
    }
}

// Aggregation layer 1 (+ self-loop + bias + ReLU): one warp per dst node.
__global__ __launch_bounds__(256) void k_agg1(const float* __restrict__ b1) {
    int node = (blockIdx.x * 256 + threadIdx.x) >> 5;
    int lane = threadIdx.x & 31;
    if (node >= NN) return;
    int off = g_off[node];
    int n   = g_deg[node];
    const float2* h1v = (const float2*)g_h1;
    float2 acc = make_float2(0.f, 0.f);
    int i = 0;
    for (; i + 4 <= n; i += 4) {
        int2 e0 = g_edge[off + i];
        int2 e1 = g_edge[off + i + 1];
        int2 e2 = g_edge[off + i + 2];
        int2 e3 = g_edge[off + i + 3];
        float2 p0 = h1v[(size_t)e0.x * 32 + lane];
        float2 p1 = h1v[(size_t)e1.x * 32 + lane];
        float2 p2 = h1v[(size_t)e2.x * 32 + lane];
        float2 p3 = h1v[(size_t)e3.x * 32 + lane];
        float n0 = __int_as_float(e0.y), n1 = __int_as_float(e1.y);
        float n2 = __int_as_float(e2.y), n3 = __int_as_float(e3.y);
        acc.x = fmaf(p0.x, n0, acc.x); acc.y = fmaf(p0.y, n0, acc.y);
        acc.x = fmaf(p1.x, n1, acc.x); acc.y = fmaf(p1.y, n1, acc.y);
        acc.x = fmaf(p2.x, n2, acc.x); acc.y = fmaf(p2.y, n2, acc.y);
        acc.x = fmaf(p3.x, n3, acc.x); acc.y = fmaf(p3.y, n3, acc.y);
    }
    for (; i < n; i++) {
        int2 e0 = g_edge[off + i];
        float2 p = h1v[(size_t)e0.x * 32 + lane];
        float n0 = __int_as_float(e0.y);
        acc.x = fmaf(p.x, n0, acc.x); acc.y = fmaf(p.y, n0, acc.y);
    }
    float di = g_dinv[node], w = di * di;
    float2 hs = h1v[(size_t)node * 32 + lane];
    float2 bb = ((const float2*)b1)[lane];
    acc.x = fmaxf(fmaf(hs.x, w, acc.x) + bb.x, 0.f);
    acc.y = fmaxf(fmaf(hs.y, w, acc.y) + bb.y, 0.f);
    ((float2*)g_a1)[(size_t)node * 32 + lane] = acc;
}

// ---------------------------------------------------------------------------
// GEMM2: h3[NN,32] = a1[NN,64] @ W2[64,32].
// 128 rows/block, 128 threads, 4 rows x 8 cols per thread, f32x2 FMA.
__global__ __launch_bounds__(128) void k_gemm2(const float* __restrict__ W) {
    __shared__ float Ws[FH * FO];    // 8 KB
    __shared__ float xs[128 * FH];   // 32 KB
    int tid = threadIdx.x;
    float4* Ws4 = (float4*)Ws;
    const float4* W4 = (const float4*)W;
    for (int i = tid; i < FH * FO / 4; i += 128) Ws4[i] = W4[i];
    int row0 = blockIdx.x * 128;
    float4* xs4 = (float4*)xs;
    const float4* x4 = (const float4*)g_a1;
    for (int i = tid; i < 128 * FH / 4; i += 128) {
        int row = row0 + (i >> 4);                 // 16 float4 per row
        xs4[i] = (row < NN) ? x4[(size_t)row * 16 + (i & 15)]
                            : make_float4(0.f, 0.f, 0.f, 0.f);
    }
    __syncthreads();

    int tx = tid & 3;               // cols 8tx..8tx+7
    int ty = tid >> 2;              // rows 4ty..4ty+3
    const float* xr = xs + 4 * ty * FH;
    const ulonglong2* Wp = (const ulonglong2*)Ws;  // 8 ulonglong2 per k-row
    unsigned long long acc[4][4] = {};
    #pragma unroll 8
    for (int k = 0; k < FH; k++) {
        ulonglong2 w01 = Wp[k * 8 + 2 * tx];
        ulonglong2 w23 = Wp[k * 8 + 2 * tx + 1];
        #pragma unroll
        for (int j = 0; j < 4; j++) {
            float a = xr[j * FH + k];
            unsigned long long aa;
            BCAST2(aa, a);
            FMA2(acc[j][0], aa, w01.x);
            FMA2(acc[j][1], aa, w01.y);
            FMA2(acc[j][2], aa, w23.x);
            FMA2(acc[j][3], aa, w23.y);
        }
    }
    ulonglong2* h3v = (ulonglong2*)g_h3;           // 8 ulonglong2 per row
    #pragma unroll
    for (int j = 0; j < 4; j++) {
        int row = row0 + 4 * ty + j;
        if (row < NN) {
            h3v[(size_t)row * 8 + 2 * tx]     = make_ulonglong2(acc[j][0], acc[j][1]);
            h3v[(size_t)row * 8 + 2 * tx + 1] = make_ulonglong2(acc[j][2], acc[j][3]);
        }
    }
}

// Aggregation layer 2 (+ self-loop + bias): one warp per dst node, writes d_out.
__global__ __launch_bounds__(256) void k_agg2(float* __restrict__ out,
                                              const float* __restrict__ b2) {
    int node = (blockIdx.x * 256 + threadIdx.x) >> 5;
    int lane = threadIdx.x & 31;
    if (node >= NN) return;
    int off = g_off[node];
    int n   = g_deg[node];
    float acc = 0.f;
    int i = 0;
    for (; i + 4 <= n; i += 4) {
        int2 e0 = g_edge[off + i];
        int2 e1 = g_edge[off + i + 1];
        int2 e2 = g_edge[off + i + 2];
        int2 e3 = g_edge[off + i + 3];
        float p0 = g_h3[(size_t)e0.x * 32 + lane];
        float p1 = g_h3[(size_t)e1.x * 32 + lane];
        float p2 = g_h3[(size_t)e2.x * 32 + lane];
        float p3 = g_h3[(size_t)e3.x * 32 + lane];
        acc = fmaf(p0, __int_as_float(e0.y), acc);
        acc = fmaf(p1, __int_as_float(e1.y), acc);
        acc = fmaf(p2, __int_as_float(e2.y), acc);
        acc = fmaf(p3, __int_as_float(e3.y), acc);
    }
    for (; i < n; i++) {
        int2 e0 = g_edge[off + i];
        acc = fmaf(g_h3[(size_t)e0.x * 32 + lane], __int_as_float(e0.y), acc);
    }
    float di = g_dinv[node], w = di * di;
    out[(size_t)node * 32 + lane] =
        fmaf(g_h3[(size_t)node * 32 + lane], w, acc) + b2[lane];
}

// ---------------------------------------------------------------------------
extern "C" void kernel_launch(void* const* d_in, const int* in_sizes, int n_in,
                              void* d_out, int out_size) {
    const float* x  = (const float*)d_in[0];
    const int*   ei = (const int*)d_in[1];     // int32 (JAX x64 disabled)
    const float* W1 = (const float*)d_in[2];
    const float* b1 = (const float*)d_in[3];
    const float* W2 = (const float*)d_in[4];
    const float* b2 = (const float*)d_in[5];
    float* out = (float*)d_out;

    const int E = in_sizes[1] / 2;

    k_init<<<(NN + 255) / 256, 256>>>();
    k_deg<<<(E + 255) / 256, 256>>>(ei, E);
    k_scan1<<<NSCAN_BLK, 512>>>();
    k_scan2<<<1, 256>>>();
    k_scan3<<<(NN + 255) / 256, 256>>>();
    k_scatter<<<(E + 255) / 256, 256>>>(ei, E);

    k_gemm1<<<(NN + 63) / 64, 128>>>(x, W1);
    k_agg1<<<(NN * 32 + 255) / 256, 256>>>(b1);

    k_gemm2<<<(NN + 127) / 128, 128>>>(W2);
    k_agg2<<<(NN * 32 + 255) / 256, 256>>>(out, b2);
}

// round 8
// speedup vs baseline: 1.3685x; 1.3685x over previous
#include <cuda_runtime.h>
#include <cstdint>

#define NN 100000
#define F1 128
#define FH 64
#define FO 32
#define EMAX 1600000
#define NSCAN_BLK 196            // ceil(100000/512)

// Scratch (no allocations allowed).
__device__ int   g_deg[NN];
__device__ int   g_cur[NN];
__device__ int   g_off[NN];
__device__ int   g_scan[NN];
__device__ int   g_bsum[NSCAN_BLK];
__device__ int   g_bsumx[NSCAN_BLK];
__device__ float g_dinv[NN];
__device__ int2  g_edge[EMAX];            // (src, norm) grouped by dst
__device__ float g_h1[(size_t)NN * FH];   // x @ W1
__device__ float g_a1[(size_t)NN * FH];   // layer-1 activations (post ReLU)
__device__ float g_h3[(size_t)NN * FO];   // a1 @ W2

#define FMA2(acc, aa, ww) \
    asm("fma.rn.f32x2 %0, %1, %2, %0;" : "+l"(acc) : "l"(aa), "l"(ww))
#define BCAST2(aa, a) \
    asm("mov.b64 %0, {%1, %1};" : "=l"(aa) : "f"(a))

// ---------------------------------------------------------------------------
__global__ void k_init() {
    int i = blockIdx.x * blockDim.x + threadIdx.x;
    if (i < NN) g_deg[i] = 0;
}

__global__ void k_deg(const int* __restrict__ ei, int E) {
    int i = blockIdx.x * blockDim.x + threadIdx.x;
    if (i < E) atomicAdd(&g_deg[ei[E + i]], 1);
}

// ---- exclusive prefix sum of g_deg -> g_off --------------------------------
__global__ __launch_bounds__(512) void k_scan1() {
    __shared__ int sh[512];
    int t = threadIdx.x;
    int i = blockIdx.x * 512 + t;
    int v = (i < NN) ? g_deg[i] : 0;
    sh[t] = v;
    for (int d = 1; d < 512; d <<= 1) {
        __syncthreads();
        int u = (t >= d) ? sh[t - d] : 0;
        __syncthreads();
        sh[t] += u;
    }
    __syncthreads();
    if (i < NN) g_scan[i] = sh[t];
    if (t == 511) g_bsum[blockIdx.x] = sh[511];
}

__global__ __launch_bounds__(256) void k_scan2() {
    __shared__ int sh[256];
    int t = threadIdx.x;
    int v = (t < NSCAN_BLK) ? g_bsum[t] : 0;
    sh[t] = v;
    for (int d = 1; d < 256; d <<= 1) {
        __syncthreads();
        int u = (t >= d) ? sh[t - d] : 0;
        __syncthreads();
        sh[t] += u;
    }
    __syncthreads();
    if (t < NSCAN_BLK) g_bsumx[t] = sh[t] - v;   // exclusive
}

// offsets + cursor reset + dinv (fused)
__global__ void k_scan3() {
    int i = blockIdx.x * blockDim.x + threadIdx.x;
    if (i >= NN) return;
    int deg = g_deg[i];
    g_off[i] = g_scan[i] - deg + g_bsumx[i >> 9];  // exclusive offset
    g_cur[i] = 0;
    g_dinv[i] = rsqrtf((float)deg + 1.0f);         // +1 self-loop
}

// Scatter edges into destination-grouped order, packing (src, norm).
__global__ void k_scatter(const int* __restrict__ ei, int E) {
    int e = blockIdx.x * blockDim.x + threadIdx.x;
    if (e >= E) return;
    int s = ei[e];
    int d = ei[E + e];
    float norm = g_dinv[s] * g_dinv[d];
    int pos = g_off[d] + atomicAdd(&g_cur[d], 1);
    g_edge[pos] = make_int2(s, __float_as_int(norm));
}

// ---------------------------------------------------------------------------
// GEMM1: h1[NN,64] = x[NN,128] @ W1[128,64].
// 64 rows/block, 256 threads, 4 rows x 4 cols per thread, FFMA2 inner math.
__global__ __launch_bounds__(256) void k_gemm1(const float* __restrict__ x,
                                               const float* __restrict__ W) {
    __shared__ float Ws[F1 * FH];   // 32 KB  [k][col]
    __shared__ float xs[64 * F1];   // 32 KB  [r][k]
    int tid = threadIdx.x;
    float4* Ws4 = (float4*)Ws;
    const float4* W4 = (const float4*)W;
    for (int i = tid; i < F1 * FH / 4; i += 256) Ws4[i] = W4[i];
    int row0 = blockIdx.x * 64;
    const float4* x4 = (const float4*)x;
    float4* xs4 = (float4*)xs;
    for (int i = tid; i < 64 * F1 / 4; i += 256) {
        int row = row0 + (i >> 5);                 // 32 float4 per row
        xs4[i] = (row < NN) ? x4[(size_t)row * 32 + (i & 31)]
                            : make_float4(0.f, 0.f, 0.f, 0.f);
    }
    __syncthreads();

    int tx = tid & 15;              // cols 4tx..4tx+3
    int ty = tid >> 4;              // rows 4ty..4ty+3
    const float* xr = xs + 4 * ty * F1;
    const ulonglong2* Wp = (const ulonglong2*)Ws;  // 16 per k-row (64 cols)
    unsigned long long acc[4][2] = {};             // 0 bits == {0.f, 0.f}
    #pragma unroll 4
    for (int k = 0; k < F1; k++) {
        ulonglong2 w = Wp[k * 16 + tx];            // cols 4tx..4tx+3
        #pragma unroll
        for (int j = 0; j < 4; j++) {
            float a = xr[j * F1 + k];
            unsigned long long aa;
            BCAST2(aa, a);
            FMA2(acc[j][0], aa, w.x);
            FMA2(acc[j][1], aa, w.y);
        }
    }
    ulonglong2* h1v = (ulonglong2*)g_h1;           // 16 per row
    #pragma unroll
    for (int j = 0; j < 4; j++) {
        int row = row0 + 4 * ty + j;
        if (row < NN) h1v[(size_t)row * 16 + tx] = make_ulonglong2(acc[j][0], acc[j][1]);
    }
}

// Aggregation layer 1 (+ self-loop + bias + ReLU): one warp per dst node.
__global__ __launch_bounds__(256) void k_agg1(const float* __restrict__ b1) {
    int node = (blockIdx.x * 256 + threadIdx.x) >> 5;
    int lane = threadIdx.x & 31;
    if (node >= NN) return;
    int off = g_off[node];
    int n   = g_deg[node];
    const float2* h1v = (const float2*)g_h1;
    float2 acc = make_float2(0.f, 0.f);
    int i = 0;
    for (; i + 1 < n; i += 2) {
        int2 e0 = g_edge[off + i];
        int2 e1 = g_edge[off + i + 1];
        float2 p = h1v[(size_t)e0.x * 32 + lane];
        float2 q = h1v[(size_t)e1.x * 32 + lane];
        float n0 = __int_as_float(e0.y), n1 = __int_as_float(e1.y);
        acc.x = fmaf(p.x, n0, acc.x); acc.y = fmaf(p.y, n0, acc.y);
        acc.x = fmaf(q.x, n1, acc.x); acc.y = fmaf(q.y, n1, acc.y);
    }
    if (i < n) {
        int2 e0 = g_edge[off + i];
        float2 p = h1v[(size_t)e0.x * 32 + lane];
        float n0 = __int_as_float(e0.y);
        acc.x = fmaf(p.x, n0, acc.x); acc.y = fmaf(p.y, n0, acc.y);
    }
    float di = g_dinv[node], w = di * di;
    float2 hs = h1v[(size_t)node * 32 + lane];
    float2 bb = ((const float2*)b1)[lane];
    acc.x = fmaxf(fmaf(hs.x, w, acc.x) + bb.x, 0.f);
    acc.y = fmaxf(fmaf(hs.y, w, acc.y) + bb.y, 0.f);
    ((float2*)g_a1)[(size_t)node * 32 + lane] = acc;
}

// ---------------------------------------------------------------------------
// GEMM2: h3[NN,32] = a1[NN,64] @ W2[64,32].
// 128 rows/block, 256 threads, 4 rows x 4 cols per thread, FFMA2 inner math.
__global__ __launch_bounds__(256) void k_gemm2(const float* __restrict__ W) {
    __shared__ float Ws[FH * FO];    // 8 KB
    __shared__ float xs[128 * FH];   // 32 KB
    int tid = threadIdx.x;
    float4* Ws4 = (float4*)Ws;
    const float4* W4 = (const float4*)W;
    for (int i = tid; i < FH * FO / 4; i += 256) Ws4[i] = W4[i];
    int row0 = blockIdx.x * 128;
    const float4* x4 = (const float4*)g_a1;
    float4* xs4 = (float4*)xs;
    for (int i = tid; i < 128 * FH / 4; i += 256) {
        int row = row0 + (i >> 4);                 // 16 float4 per row
        xs4[i] = (row < NN) ? x4[(size_t)row * 16 + (i & 15)]
                            : make_float4(0.f, 0.f, 0.f, 0.f);
    }
    __syncthreads();

    int tx = tid & 7;               // cols 4tx..4tx+3
    int ty = tid >> 3;              // rows 4ty..4ty+3
    const float* xr = xs + 4 * ty * FH;
    const ulonglong2* Wp = (const ulonglong2*)Ws;  // 8 per k-row (32 cols)
    unsigned long long acc[4][2] = {};
    #pragma unroll 4
    for (int k = 0; k < FH; k++) {
        ulonglong2 w = Wp[k * 8 + tx];
        #pragma unroll
        for (int j = 0; j < 4; j++) {
            float a = xr[j * FH + k];
            unsigned long long aa;
            BCAST2(aa, a);
            FMA2(acc[j][0], aa, w.x);
            FMA2(acc[j][1], aa, w.y);
        }
    }
    ulonglong2* h3v = (ulonglong2*)g_h3;           // 8 per row
    #pragma unroll
    for (int j = 0; j < 4; j++) {
        int row = row0 + 4 * ty + j;
        if (row < NN) h3v[(size_t)row * 8 + tx] = make_ulonglong2(acc[j][0], acc[j][1]);
    }
}

// Aggregation layer 2 (+ self-loop + bias): one warp per dst node, writes d_out.
__global__ __launch_bounds__(256) void k_agg2(float* __restrict__ out,
                                              const float* __restrict__ b2) {
    int node = (blockIdx.x * 256 + threadIdx.x) >> 5;
    int lane = threadIdx.x & 31;
    if (node >= NN) return;
    int off = g_off[node];
    int n   = g_deg[node];
    float acc = 0.f;
    int i = 0;
    for (; i + 1 < n; i += 2) {
        int2 e0 = g_edge[off + i];
        int2 e1 = g_edge[off + i + 1];
        float p = g_h3[(size_t)e0.x * 32 + lane];
        float q = g_h3[(size_t)e1.x * 32 + lane];
        acc = fmaf(p, __int_as_float(e0.y), acc);
        acc = fmaf(q, __int_as_float(e1.y), acc);
    }
    if (i < n) {
        int2 e0 = g_edge[off + i];
        acc = fmaf(g_h3[(size_t)e0.x * 32 + lane], __int_as_float(e0.y), acc);
    }
    float di = g_dinv[node], w = di * di;
    out[(size_t)node * 32 + lane] =
        fmaf(g_h3[(size_t)node * 32 + lane], w, acc) + b2[lane];
}

// ---------------------------------------------------------------------------
extern "C" void kernel_launch(void* const* d_in, const int* in_sizes, int n_in,
                              void* d_out, int out_size) {
    const float* x  = (const float*)d_in[0];
    const int*   ei = (const int*)d_in[1];     // int32 (JAX x64 disabled)
    const float* W1 = (const float*)d_in[2];
    const float* b1 = (const float*)d_in[3];
    const float* W2 = (const float*)d_in[4];
    const float* b2 = (const float*)d_in[5];
    float* out = (float*)d_out;

    const int E = in_sizes[1] / 2;

    k_init<<<(NN + 255) / 256, 256>>>();
    k_deg<<<(E + 255) / 256, 256>>>(ei, E);
    k_scan1<<<NSCAN_BLK, 512>>>();
    k_scan2<<<1, 256>>>();
    k_scan3<<<(NN + 255) / 256, 256>>>();
    k_scatter<<<(E + 255) / 256, 256>>>(ei, E);

    k_gemm1<<<(NN + 63) / 64, 256>>>(x, W1);
    k_agg1<<<(NN * 32 + 255) / 256, 256>>>(b1);

    k_gemm2<<<(NN + 127) / 128, 256>>>(W2);
    k_agg2<<<(NN * 32 + 255) / 256, 256>>>(out, b2);
}

// round 9
// speedup vs baseline: 1.5281x; 1.1166x over previous
#include <cuda_runtime.h>
#include <cstdint>

#define NN 100000
#define F1 128
#define FH 64
#define FO 32
#define EMAX 1600000
#define NSCAN_BLK 196            // ceil(100000/512)

// Scratch (no allocations allowed).
__device__ int   g_deg[NN];                     // zero at load; re-zeroed by k_scatter
__device__ int   g_cur[NN];
__device__ int   g_off[NN + 1];
__device__ unsigned long long g_lb[NSCAN_BLK];  // lookback: (flag<<32)|value; zeroed by k_scatter
__device__ float g_dinv[NN];
__device__ int2  g_edge[EMAX];                  // (src, norm) grouped by dst
__device__ float g_h1[(size_t)NN * FH];         // x @ W1
__device__ float g_a1[(size_t)NN * FH];         // layer-1 activations (post ReLU)
__device__ float g_h3[(size_t)NN * FO];         // a1 @ W2

#define FMA2(acc, aa, ww) \
    asm("fma.rn.f32x2 %0, %1, %2, %0;" : "+l"(acc) : "l"(aa), "l"(ww))
#define BCAST2(aa, a) \
    asm("mov.b64 %0, {%1, %1};" : "=l"(aa) : "f"(a))

// ---------------------------------------------------------------------------
__global__ void k_deg(const int* __restrict__ ei, int E) {
    int i = blockIdx.x * blockDim.x + threadIdx.x;
    if (i < E) atomicAdd(&g_deg[ei[E + i]], 1);
}

// Single-pass decoupled-lookback exclusive scan of g_deg -> g_off,
// fused with cursor reset and dinv computation.
__global__ __launch_bounds__(512) void k_scan() {
    __shared__ int sh[512];
    __shared__ int s_prev;
    int t = threadIdx.x;
    int b = blockIdx.x;
    int i = b * 512 + t;
    int deg = (i < NN) ? g_deg[i] : 0;
    sh[t] = deg;
    for (int d = 1; d < 512; d <<= 1) {
        __syncthreads();
        int u = (t >= d) ? sh[t - d] : 0;
        __syncthreads();
        sh[t] += u;
    }
    __syncthreads();
    int agg = sh[511];

    if (t == 0) {
        if (b == 0) atomicExch(&g_lb[0], (2ULL << 32) | (unsigned)agg);
        else        atomicExch(&g_lb[b], (1ULL << 32) | (unsigned)agg);
    }

    if (b > 0 && t < 32) {                 // warp-parallel lookback
        int excl = 0;
        int hi = b - 1;
        for (;;) {
            int idx = hi - t;
            unsigned long long w = 0;
            if (idx >= 0) w = *(volatile unsigned long long*)&g_lb[idx];
            unsigned f = (idx >= 0) ? (unsigned)(w >> 32) : 2u;
            if (__ballot_sync(0xffffffffu, f == 0u)) continue;   // retry window
            int v = (int)(unsigned)(w & 0xffffffffULL);
            unsigned haspfx = __ballot_sync(0xffffffffu, f == 2u && idx >= 0);
            if (haspfx) {
                int first = __ffs(haspfx) - 1;   // nearest lane with a prefix
                int contrib = (idx >= 0 && t <= first) ? v : 0;
                #pragma unroll
                for (int o = 16; o; o >>= 1) contrib += __shfl_down_sync(0xffffffffu, contrib, o);
                excl += __shfl_sync(0xffffffffu, contrib, 0);
                break;
            } else {
                int contrib = (idx >= 0) ? v : 0;
                #pragma unroll
                for (int o = 16; o; o >>= 1) contrib += __shfl_down_sync(0xffffffffu, contrib, o);
                excl += __shfl_sync(0xffffffffu, contrib, 0);
                hi -= 32;
            }
        }
        if (t == 0) {
            s_prev = excl;
            atomicExch(&g_lb[b], (2ULL << 32) | (unsigned)(excl + agg));
        }
    } else if (b == 0 && t == 0) {
        s_prev = 0;
    }
    __syncthreads();

    if (i < NN) {
        g_off[i] = s_prev + sh[t] - deg;   // exclusive
        g_cur[i] = 0;
        g_dinv[i] = rsqrtf((float)deg + 1.0f);   // +1 self-loop
    }
    if (b == NSCAN_BLK - 1 && t == 511) g_off[NN] = s_prev + sh[511];
}

// Scatter edges into destination-grouped order; also reset deg/lookback state
// so the next call (graph replay) starts from the module-load invariant.
__global__ void k_scatter(const int* __restrict__ ei, int E) {
    int e = blockIdx.x * blockDim.x + threadIdx.x;
    if (e >= E) return;
    int s = ei[e];
    int d = ei[E + e];
    float norm = g_dinv[s] * g_dinv[d];
    int pos = g_off[d] + atomicAdd(&g_cur[d], 1);
    g_edge[pos] = make_int2(s, __float_as_int(norm));
    if (e < NN) g_deg[e] = 0;
    if (e < NSCAN_BLK) g_lb[e] = 0ULL;
}

// ---------------------------------------------------------------------------
// GEMM1: h1[NN,64] = x[NN,128] @ W1[128,64].
// 64 rows/block, 256 threads, 4 rows x 4 cols per thread, FFMA2 inner math.
__global__ __launch_bounds__(256) void k_gemm1(const float* __restrict__ x,
                                               const float* __restrict__ W) {
    __shared__ float Ws[F1 * FH];   // 32 KB  [k][col]
    __shared__ float xs[64 * F1];   // 32 KB  [r][k]
    int tid = threadIdx.x;
    float4* Ws4 = (float4*)Ws;
    const float4* W4 = (const float4*)W;
    for (int i = tid; i < F1 * FH / 4; i += 256) Ws4[i] = W4[i];
    int row0 = blockIdx.x * 64;
    const float4* x4 = (const float4*)x;
    float4* xs4 = (float4*)xs;
    for (int i = tid; i < 64 * F1 / 4; i += 256) {
        int row = row0 + (i >> 5);                 // 32 float4 per row
        xs4[i] = (row < NN) ? x4[(size_t)row * 32 + (i & 31)]
                            : make_float4(0.f, 0.f, 0.f, 0.f);
    }
    __syncthreads();

    int tx = tid & 15;              // cols 4tx..4tx+3
    int ty = tid >> 4;              // rows 4ty..4ty+3
    const float* xr = xs + 4 * ty * F1;
    const ulonglong2* Wp = (const ulonglong2*)Ws;  // 16 per k-row (64 cols)
    unsigned long long acc[4][2] = {};             // 0 bits == {0.f, 0.f}
    #pragma unroll 4
    for (int k = 0; k < F1; k++) {
        ulonglong2 w = Wp[k * 16 + tx];            // cols 4tx..4tx+3
        #pragma unroll
        for (int j = 0; j < 4; j++) {
            float a = xr[j * F1 + k];
            unsigned long long aa;
            BCAST2(aa, a);
            FMA2(acc[j][0], aa, w.x);
            FMA2(acc[j][1], aa, w.y);
        }
    }
    ulonglong2* h1v = (ulonglong2*)g_h1;           // 16 per row
    #pragma unroll
    for (int j = 0; j < 4; j++) {
        int row = row0 + 4 * ty + j;
        if (row < NN) h1v[(size_t)row * 16 + tx] = make_ulonglong2(acc[j][0], acc[j][1]);
    }
}

// Aggregation layer 1 (+ self-loop + bias + ReLU): 16 lanes per dst node,
// one float4 per lane per edge (LDG.128 gathers).
__global__ __launch_bounds__(256) void k_agg1(const float* __restrict__ b1) {
    int gid = blockIdx.x * 256 + threadIdx.x;
    int node = gid >> 4;
    int lane = threadIdx.x & 15;
    if (node >= NN) return;
    int off = g_off[node];
    int n   = g_off[node + 1] - off;
    const float4* h1v = (const float4*)g_h1;   // 16 float4 per row
    float4 acc = make_float4(0.f, 0.f, 0.f, 0.f);
    int i = 0;
    for (; i + 1 < n; i += 2) {
        int2 e0 = g_edge[off + i];
        int2 e1 = g_edge[off + i + 1];
        float4 p = h1v[(size_t)e0.x * 16 + lane];
        float4 q = h1v[(size_t)e1.x * 16 + lane];
        float n0 = __int_as_float(e0.y), n1 = __int_as_float(e1.y);
        acc.x = fmaf(p.x, n0, acc.x); acc.y = fmaf(p.y, n0, acc.y);
        acc.z = fmaf(p.z, n0, acc.z); acc.w = fmaf(p.w, n0, acc.w);
        acc.x = fmaf(q.x, n1, acc.x); acc.y = fmaf(q.y, n1, acc.y);
        acc.z = fmaf(q.z, n1, acc.z); acc.w = fmaf(q.w, n1, acc.w);
    }
    if (i < n) {
        int2 e0 = g_edge[off + i];
        float4 p = h1v[(size_t)e0.x * 16 + lane];
        float n0 = __int_as_float(e0.y);
        acc.x = fmaf(p.x, n0, acc.x); acc.y = fmaf(p.y, n0, acc.y);
        acc.z = fmaf(p.z, n0, acc.z); acc.w = fmaf(p.w, n0, acc.w);
    }
    float di = g_dinv[node], w = di * di;
    float4 hs = h1v[(size_t)node * 16 + lane];
    float4 bb = ((const float4*)b1)[lane];
    acc.x = fmaxf(fmaf(hs.x, w, acc.x) + bb.x, 0.f);
    acc.y = fmaxf(fmaf(hs.y, w, acc.y) + bb.y, 0.f);
    acc.z = fmaxf(fmaf(hs.z, w, acc.z) + bb.z, 0.f);
    acc.w = fmaxf(fmaf(hs.w, w, acc.w) + bb.w, 0.f);
    ((float4*)g_a1)[(size_t)node * 16 + lane] = acc;
}

// ---------------------------------------------------------------------------
// GEMM2: h3[NN,32] = a1[NN,64] @ W2[64,32].
// 128 rows/block, 256 threads, 4 rows x 4 cols per thread, FFMA2 inner math.
__global__ __launch_bounds__(256) void k_gemm2(const float* __restrict__ W) {
    __shared__ float Ws[FH * FO];    // 8 KB
    __shared__ float xs[128 * FH];   // 32 KB
    int tid = threadIdx.x;
    float4* Ws4 = (float4*)Ws;
    const float4* W4 = (const float4*)W;
    for (int i = tid; i < FH * FO / 4; i += 256) Ws4[i] = W4[i];
    int row0 = blockIdx.x * 128;
    const float4* x4 = (const float4*)g_a1;
    float4* xs4 = (float4*)xs;
    for (int i = tid; i < 128 * FH / 4; i += 256) {
        int row = row0 + (i >> 4);                 // 16 float4 per row
        xs4[i] = (row < NN) ? x4[(size_t)row * 16 + (i & 15)]
                            : make_float4(0.f, 0.f, 0.f, 0.f);
    }
    __syncthreads();

    int tx = tid & 7;               // cols 4tx..4tx+3
    int ty = tid >> 3;              // rows 4ty..4ty+3
    const float* xr = xs + 4 * ty * FH;
    const ulonglong2* Wp = (const ulonglong2*)Ws;  // 8 per k-row (32 cols)
    unsigned long long acc[4][2] = {};
    #pragma unroll 4
    for (int k = 0; k < FH; k++) {
        ulonglong2 w = Wp[k * 8 + tx];
        #pragma unroll
        for (int j = 0; j < 4; j++) {
            float a = xr[j * FH + k];
            unsigned long long aa;
            BCAST2(aa, a);
            FMA2(acc[j][0], aa, w.x);
            FMA2(acc[j][1], aa, w.y);
        }
    }
    ulonglong2* h3v = (ulonglong2*)g_h3;           // 8 per row
    #pragma unroll
    for (int j = 0; j < 4; j++) {
        int row = row0 + 4 * ty + j;
        if (row < NN) h3v[(size_t)row * 8 + tx] = make_ulonglong2(acc[j][0], acc[j][1]);
    }
}

// Aggregation layer 2 (+ self-loop + bias): 8 lanes per dst node, float4 per
// lane per edge, plain store into d_out.
__global__ __launch_bounds__(256) void k_agg2(float* __restrict__ out,
                                              const float* __restrict__ b2) {
    int gid = blockIdx.x * 256 + threadIdx.x;
    int node = gid >> 3;
    int lane = threadIdx.x & 7;
    if (node >= NN) return;
    int off = g_off[node];
    int n   = g_off[node + 1] - off;
    const float4* h3v = (const float4*)g_h3;   // 8 float4 per row
    float4 acc = make_float4(0.f, 0.f, 0.f, 0.f);
    int i = 0;
    for (; i + 1 < n; i += 2) {
        int2 e0 = g_edge[off + i];
        int2 e1 = g_edge[off + i + 1];
        float4 p = h3v[(size_t)e0.x * 8 + lane];
        float4 q = h3v[(size_t)e1.x * 8 + lane];
        float n0 = __int_as_float(e0.y), n1 = __int_as_float(e1.y);
        acc.x = fmaf(p.x, n0, acc.x); acc.y = fmaf(p.y, n0, acc.y);
        acc.z = fmaf(p.z, n0, acc.z); acc.w = fmaf(p.w, n0, acc.w);
        acc.x = fmaf(q.x, n1, acc.x); acc.y = fmaf(q.y, n1, acc.y);
        acc.z = fmaf(q.z, n1, acc.z); acc.w = fmaf(q.w, n1, acc.w);
    }
    if (i < n) {
        int2 e0 = g_edge[off + i];
        float4 p = h3v[(size_t)e0.x * 8 + lane];
        float n0 = __int_as_float(e0.y);
        acc.x = fmaf(p.x, n0, acc.x); acc.y = fmaf(p.y, n0, acc.y);
        acc.z = fmaf(p.z, n0, acc.z); acc.w = fmaf(p.w, n0, acc.w);
    }
    float di = g_dinv[node], w = di * di;
    float4 hs = h3v[(size_t)node * 8 + lane];
    float4 bb = ((const float4*)b2)[lane];
    acc.x = fmaf(hs.x, w, acc.x) + bb.x;
    acc.y = fmaf(hs.y, w, acc.y) + bb.y;
    acc.z = fmaf(hs.z, w, acc.z) + bb.z;
    acc.w = fmaf(hs.w, w, acc.w) + bb.w;
    ((float4*)out)[(size_t)node * 8 + lane] = acc;
}

// ---------------------------------------------------------------------------
extern "C" void kernel_launch(void* const* d_in, const int* in_sizes, int n_in,
                              void* d_out, int out_size) {
    const float* x  = (const float*)d_in[0];
    const int*   ei = (const int*)d_in[1];     // int32 (JAX x64 disabled)
    const float* W1 = (const float*)d_in[2];
    const float* b1 = (const float*)d_in[3];
    const float* W2 = (const float*)d_in[4];
    const float* b2 = (const float*)d_in[5];
    float* out = (float*)d_out;

    const int E = in_sizes[1] / 2;

    k_deg<<<(E + 255) / 256, 256>>>(ei, E);
    k_scan<<<NSCAN_BLK, 512>>>();
    k_scatter<<<(E + 255) / 256, 256>>>(ei, E);

    k_gemm1<<<(NN + 63) / 64, 256>>>(x, W1);
    k_agg1<<<(NN * 16 + 255) / 256, 256>>>(b1);

    k_gemm2<<<(NN + 127) / 128, 256>>>(W2);
    k_agg2<<<(NN * 8 + 255) / 256, 256>>>(out, b2);
}

// round 10
// speedup vs baseline: 1.5642x; 1.0237x over previous
#include <cuda_runtime.h>
#include <cstdint>

#define NN 100000
#define F1 128
#define FH 64
#define FO 32
#define EMAX 1600000
#define NSCAN_BLK 196            // ceil(100000/512)

// Scratch (no allocations allowed).
__device__ int   g_deg[NN];                     // zero at load; re-zeroed by k_scatter
__device__ int   g_cur[NN];
__device__ int   g_off[NN + 1];
__device__ unsigned long long g_lb[NSCAN_BLK];  // lookback: (flag<<32)|value; zeroed by k_scatter
__device__ float g_dinv[NN];
__device__ int2  g_edge[EMAX];                  // (src, norm) grouped by dst
__device__ float g_h1[(size_t)NN * FH];         // x @ W1
__device__ float g_a1[(size_t)NN * FH];         // layer-1 activations (post ReLU)
__device__ float g_h3[(size_t)NN * FO];         // a1 @ W2

#define FMA2(acc, aa, ww) \
    asm("fma.rn.f32x2 %0, %1, %2, %0;" : "+l"(acc) : "l"(aa), "l"(ww))
#define BCAST2(aa, a) \
    asm("mov.b64 %0, {%1, %1};" : "=l"(aa) : "f"(a))

// ---------------------------------------------------------------------------
__global__ void k_deg(const int* __restrict__ ei, int E) {
    int i = blockIdx.x * blockDim.x + threadIdx.x;
    if (i < E) atomicAdd(&g_deg[ei[E + i]], 1);
}

// Single-pass decoupled-lookback exclusive scan of g_deg -> g_off,
// fused with cursor reset and dinv computation.
__global__ __launch_bounds__(512) void k_scan() {
    __shared__ int sh[512];
    __shared__ int s_prev;
    int t = threadIdx.x;
    int b = blockIdx.x;
    int i = b * 512 + t;
    int deg = (i < NN) ? g_deg[i] : 0;
    sh[t] = deg;
    for (int d = 1; d < 512; d <<= 1) {
        __syncthreads();
        int u = (t >= d) ? sh[t - d] : 0;
        __syncthreads();
        sh[t] += u;
    }
    __syncthreads();
    int agg = sh[511];

    if (t == 0) {
        if (b == 0) atomicExch(&g_lb[0], (2ULL << 32) | (unsigned)agg);
        else        atomicExch(&g_lb[b], (1ULL << 32) | (unsigned)agg);
    }

    if (b > 0 && t < 32) {                 // warp-parallel lookback
        int excl = 0;
        int hi = b - 1;
        for (;;) {
            int idx = hi - t;
            unsigned long long w = 0;
            if (idx >= 0) w = *(volatile unsigned long long*)&g_lb[idx];
            unsigned f = (idx >= 0) ? (unsigned)(w >> 32) : 2u;
            if (__ballot_sync(0xffffffffu, f == 0u)) continue;   // retry window
            int v = (int)(unsigned)(w & 0xffffffffULL);
            unsigned haspfx = __ballot_sync(0xffffffffu, f == 2u && idx >= 0);
            if (haspfx) {
                int first = __ffs(haspfx) - 1;   // nearest lane with a prefix
                int contrib = (idx >= 0 && t <= first) ? v : 0;
                #pragma unroll
                for (int o = 16; o; o >>= 1) contrib += __shfl_down_sync(0xffffffffu, contrib, o);
                excl += __shfl_sync(0xffffffffu, contrib, 0);
                break;
            } else {
                int contrib = (idx >= 0) ? v : 0;
                #pragma unroll
                for (int o = 16; o; o >>= 1) contrib += __shfl_down_sync(0xffffffffu, contrib, o);
                excl += __shfl_sync(0xffffffffu, contrib, 0);
                hi -= 32;
            }
        }
        if (t == 0) {
            s_prev = excl;
            atomicExch(&g_lb[b], (2ULL << 32) | (unsigned)(excl + agg));
        }
    } else if (b == 0 && t == 0) {
        s_prev = 0;
    }
    __syncthreads();

    if (i < NN) {
        g_off[i] = s_prev + sh[t] - deg;   // exclusive
        g_cur[i] = 0;
        g_dinv[i] = rsqrtf((float)deg + 1.0f);   // +1 self-loop
    }
    if (b == NSCAN_BLK - 1 && t == 511) g_off[NN] = s_prev + sh[511];
}

// Scatter edges into destination-grouped order; also reset deg/lookback state
// so the next call (graph replay) starts from the module-load invariant.
__global__ void k_scatter(const int* __restrict__ ei, int E) {
    int e = blockIdx.x * blockDim.x + threadIdx.x;
    if (e >= E) return;
    int s = ei[e];
    int d = ei[E + e];
    float norm = g_dinv[s] * g_dinv[d];
    int pos = g_off[d] + atomicAdd(&g_cur[d], 1);
    g_edge[pos] = make_int2(s, __float_as_int(norm));
    if (e < NN) g_deg[e] = 0;
    if (e < NSCAN_BLK) g_lb[e] = 0ULL;
}

// ---------------------------------------------------------------------------
// GEMM1: h1[NN,64] = x[NN,128] @ W1[128,64].
// 64 rows/block, 256 threads, 4 rows x 4 cols per thread, FFMA2 math,
// K chunked by 4 with float4 activation loads (fewer LDS wavefronts).
__global__ __launch_bounds__(256) void k_gemm1(const float* __restrict__ x,
                                               const float* __restrict__ W) {
    __shared__ float Ws[F1 * FH];   // 32 KB  [k][col]
    __shared__ float xs[64 * F1];   // 32 KB  [r][k]
    int tid = threadIdx.x;
    float4* Ws4 = (float4*)Ws;
    const float4* W4 = (const float4*)W;
    for (int i = tid; i < F1 * FH / 4; i += 256) Ws4[i] = W4[i];
    int row0 = blockIdx.x * 64;
    const float4* x4 = (const float4*)x;
    float4* xs4 = (float4*)xs;
    for (int i = tid; i < 64 * F1 / 4; i += 256) {
        int row = row0 + (i >> 5);                 // 32 float4 per row
        xs4[i] = (row < NN) ? x4[(size_t)row * 32 + (i & 31)]
                            : make_float4(0.f, 0.f, 0.f, 0.f);
    }
    __syncthreads();

    int tx = tid & 15;              // cols 4tx..4tx+3
    int ty = tid >> 4;              // rows 4ty..4ty+3
    const float* xr = xs + 4 * ty * F1;
    const ulonglong2* Wp = (const ulonglong2*)Ws;  // 16 per k-row (64 cols)
    unsigned long long acc[4][2] = {};             // 0 bits == {0.f, 0.f}

    #define G1_STEP(KK, CMP)                                               \
        do {                                                               \
            ulonglong2 w = Wp[(k + KK) * 16 + tx];                         \
            unsigned long long aa;                                         \
            BCAST2(aa, a0.CMP); FMA2(acc[0][0], aa, w.x); FMA2(acc[0][1], aa, w.y); \
            BCAST2(aa, a1.CMP); FMA2(acc[1][0], aa, w.x); FMA2(acc[1][1], aa, w.y); \
            BCAST2(aa, a2.CMP); FMA2(acc[2][0], aa, w.x); FMA2(acc[2][1], aa, w.y); \
            BCAST2(aa, a3.CMP); FMA2(acc[3][0], aa, w.x); FMA2(acc[3][1], aa, w.y); \
        } while (0)

    #pragma unroll 4
    for (int k = 0; k < F1; k += 4) {
        float4 a0 = *(const float4*)(xr + 0 * F1 + k);
        float4 a1 = *(const float4*)(xr + 1 * F1 + k);
        float4 a2 = *(const float4*)(xr + 2 * F1 + k);
        float4 a3 = *(const float4*)(xr + 3 * F1 + k);
        G1_STEP(0, x); G1_STEP(1, y); G1_STEP(2, z); G1_STEP(3, w);
    }
    #undef G1_STEP

    ulonglong2* h1v = (ulonglong2*)g_h1;           // 16 per row
    #pragma unroll
    for (int j = 0; j < 4; j++) {
        int row = row0 + 4 * ty + j;
        if (row < NN) h1v[(size_t)row * 16 + tx] = make_ulonglong2(acc[j][0], acc[j][1]);
    }
}

// Aggregation layer 1 (+ self-loop + bias + ReLU): 16 lanes per dst node,
// one float4 per lane per edge (LDG.128 gathers).
__global__ __launch_bounds__(256) void k_agg1(const float* __restrict__ b1) {
    int gid = blockIdx.x * 256 + threadIdx.x;
    int node = gid >> 4;
    int lane = threadIdx.x & 15;
    if (node >= NN) return;
    int off = g_off[node];
    int n   = g_off[node + 1] - off;
    const float4* h1v = (const float4*)g_h1;   // 16 float4 per row
    float4 acc = make_float4(0.f, 0.f, 0.f, 0.f);
    int i = 0;
    for (; i + 1 < n; i += 2) {
        int2 e0 = g_edge[off + i];
        int2 e1 = g_edge[off + i + 1];
        float4 p = h1v[(size_t)e0.x * 16 + lane];
        float4 q = h1v[(size_t)e1.x * 16 + lane];
        float n0 = __int_as_float(e0.y), n1 = __int_as_float(e1.y);
        acc.x = fmaf(p.x, n0, acc.x); acc.y = fmaf(p.y, n0, acc.y);
        acc.z = fmaf(p.z, n0, acc.z); acc.w = fmaf(p.w, n0, acc.w);
        acc.x = fmaf(q.x, n1, acc.x); acc.y = fmaf(q.y, n1, acc.y);
        acc.z = fmaf(q.z, n1, acc.z); acc.w = fmaf(q.w, n1, acc.w);
    }
    if (i < n) {
        int2 e0 = g_edge[off + i];
        float4 p = h1v[(size_t)e0.x * 16 + lane];
        float n0 = __int_as_float(e0.y);
        acc.x = fmaf(p.x, n0, acc.x); acc.y = fmaf(p.y, n0, acc.y);
        acc.z = fmaf(p.z, n0, acc.z); acc.w = fmaf(p.w, n0, acc.w);
    }
    float di = g_dinv[node], w = di * di;
    float4 hs = h1v[(size_t)node * 16 + lane];
    float4 bb = ((const float4*)b1)[lane];
    acc.x = fmaxf(fmaf(hs.x, w, acc.x) + bb.x, 0.f);
    acc.y = fmaxf(fmaf(hs.y, w, acc.y) + bb.y, 0.f);
    acc.z = fmaxf(fmaf(hs.z, w, acc.z) + bb.z, 0.f);
    acc.w = fmaxf(fmaf(hs.w, w, acc.w) + bb.w, 0.f);
    ((float4*)g_a1)[(size_t)node * 16 + lane] = acc;
}

// ---------------------------------------------------------------------------
// GEMM2: h3[NN,32] = a1[NN,64] @ W2[64,32].
// 128 rows/block, 256 threads, 4 rows x 4 cols per thread, FFMA2 math,
// K chunked by 4 with float4 activation loads.
__global__ __launch_bounds__(256) void k_gemm2(const float* __restrict__ W) {
    __shared__ float Ws[FH * FO];    // 8 KB
    __shared__ float xs[128 * FH];   // 32 KB
    int tid = threadIdx.x;
    float4* Ws4 = (float4*)Ws;
    const float4* W4 = (const float4*)W;
    for (int i = tid; i < FH * FO / 4; i += 256) Ws4[i] = W4[i];
    int row0 = blockIdx.x * 128;
    const float4* x4 = (const float4*)g_a1;
    float4* xs4 = (float4*)xs;
    for (int i = tid; i < 128 * FH / 4; i += 256) {
        int row = row0 + (i >> 4);                 // 16 float4 per row
        xs4[i] = (row < NN) ? x4[(size_t)row * 16 + (i & 15)]
                            : make_float4(0.f, 0.f, 0.f, 0.f);
    }
    __syncthreads();

    int tx = tid & 7;               // cols 4tx..4tx+3
    int ty = tid >> 3;              // rows 4ty..4ty+3
    const float* xr = xs + 4 * ty * FH;
    const ulonglong2* Wp = (const ulonglong2*)Ws;  // 8 per k-row (32 cols)
    unsigned long long acc[4][2] = {};

    #define G2_STEP(KK, CMP)                                               \
        do {                                                               \
            ulonglong2 w = Wp[(k + KK) * 8 + tx];                          \
            unsigned long long aa;                                         \
            BCAST2(aa, a0.CMP); FMA2(acc[0][0], aa, w.x); FMA2(acc[0][1], aa, w.y); \
            BCAST2(aa, a1.CMP); FMA2(acc[1][0], aa, w.x); FMA2(acc[1][1], aa, w.y); \
            BCAST2(aa, a2.CMP); FMA2(acc[2][0], aa, w.x); FMA2(acc[2][1], aa, w.y); \
            BCAST2(aa, a3.CMP); FMA2(acc[3][0], aa, w.x); FMA2(acc[3][1], aa, w.y); \
        } while (0)

    #pragma unroll 4
    for (int k = 0; k < FH; k += 4) {
        float4 a0 = *(const float4*)(xr + 0 * FH + k);
        float4 a1 = *(const float4*)(xr + 1 * FH + k);
        float4 a2 = *(const float4*)(xr + 2 * FH + k);
        float4 a3 = *(const float4*)(xr + 3 * FH + k);
        G2_STEP(0, x); G2_STEP(1, y); G2_STEP(2, z); G2_STEP(3, w);
    }
    #undef G2_STEP

    ulonglong2* h3v = (ulonglong2*)g_h3;           // 8 per row
    #pragma unroll
    for (int j = 0; j < 4; j++) {
        int row = row0 + 4 * ty + j;
        if (row < NN) h3v[(size_t)row * 8 + tx] = make_ulonglong2(acc[j][0], acc[j][1]);
    }
}

// Aggregation layer 2 (+ self-loop + bias): 8 lanes per dst node, float4 per
// lane per edge, plain store into d_out.
__global__ __launch_bounds__(256) void k_agg2(float* __restrict__ out,
                                              const float* __restrict__ b2) {
    int gid = blockIdx.x * 256 + threadIdx.x;
    int node = gid >> 3;
    int lane = threadIdx.x & 7;
    if (node >= NN) return;
    int off = g_off[node];
    int n   = g_off[node + 1] - off;
    const float4* h3v = (const float4*)g_h3;   // 8 float4 per row
    float4 acc = make_float4(0.f, 0.f, 0.f, 0.f);
    int i = 0;
    for (; i + 1 < n; i += 2) {
        int2 e0 = g_edge[off + i];
        int2 e1 = g_edge[off + i + 1];
        float4 p = h3v[(size_t)e0.x * 8 + lane];
        float4 q = h3v[(size_t)e1.x * 8 + lane];
        float n0 = __int_as_float(e0.y), n1 = __int_as_float(e1.y);
        acc.x = fmaf(p.x, n0, acc.x); acc.y = fmaf(p.y, n0, acc.y);
        acc.z = fmaf(p.z, n0, acc.z); acc.w = fmaf(p.w, n0, acc.w);
        acc.x = fmaf(q.x, n1, acc.x); acc.y = fmaf(q.y, n1, acc.y);
        acc.z = fmaf(q.z, n1, acc.z); acc.w = fmaf(q.w, n1, acc.w);
    }
    if (i < n) {
        int2 e0 = g_edge[off + i];
        float4 p = h3v[(size_t)e0.x * 8 + lane];
        float n0 = __int_as_float(e0.y);
        acc.x = fmaf(p.x, n0, acc.x); acc.y = fmaf(p.y, n0, acc.y);
        acc.z = fmaf(p.z, n0, acc.z); acc.w = fmaf(p.w, n0, acc.w);
    }
    float di = g_dinv[node], w = di * di;
    float4 hs = h3v[(size_t)node * 8 + lane];
    float4 bb = ((const float4*)b2)[lane];
    acc.x = fmaf(hs.x, w, acc.x) + bb.x;
    acc.y = fmaf(hs.y, w, acc.y) + bb.y;
    acc.z = fmaf(hs.z, w, acc.z) + bb.z;
    acc.w = fmaf(hs.w, w, acc.w) + bb.w;
    ((float4*)out)[(size_t)node * 8 + lane] = acc;
}

// ---------------------------------------------------------------------------
extern "C" void kernel_launch(void* const* d_in, const int* in_sizes, int n_in,
                              void* d_out, int out_size) {
    const float* x  = (const float*)d_in[0];
    const int*   ei = (const int*)d_in[1];     // int32 (JAX x64 disabled)
    const float* W1 = (const float*)d_in[2];
    const float* b1 = (const float*)d_in[3];
    const float* W2 = (const float*)d_in[4];
    const float* b2 = (const float*)d_in[5];
    float* out = (float*)d_out;

    const int E = in_sizes[1] / 2;

    k_deg<<<(E + 255) / 256, 256>>>(ei, E);
    k_scan<<<NSCAN_BLK, 512>>>();
    k_scatter<<<(E + 255) / 256, 256>>>(ei, E);

    k_gemm1<<<(NN + 63) / 64, 256>>>(x, W1);
    k_agg1<<<(NN * 16 + 255) / 256, 256>>>(b1);

    k_gemm2<<<(NN + 127) / 128, 256>>>(W2);
    k_agg2<<<(NN * 8 + 255) / 256, 256>>>(out, b2);
}

// round 11
// speedup vs baseline: 1.6232x; 1.0377x over previous
#include <cuda_runtime.h>
#include <cstdint>

#define NN 100000
#define F1 128
#define FH 64
#define FO 32
#define EMAX 1600000
#define NSCAN_BLK 196            // ceil(100000/512)

// Scratch (no allocations allowed).
__device__ int   g_deg[NN];                     // zero at load; re-zeroed by k_scatter
__device__ int   g_cur[NN];
__device__ int   g_off[NN + 1];
__device__ unsigned long long g_lb[NSCAN_BLK];  // lookback: (flag<<32)|value; zeroed by k_scatter
__device__ float g_dinv[NN];
__device__ int2  g_edge[EMAX];                  // (src, norm) grouped by dst
__device__ float g_h1[(size_t)NN * FH];         // x @ W1
__device__ float g_a1[(size_t)NN * FH];         // layer-1 activations (post ReLU)
__device__ float g_h3[(size_t)NN * FO];         // a1 @ W2

#define FMA2(acc, aa, ww) \
    asm("fma.rn.f32x2 %0, %1, %2, %0;" : "+l"(acc) : "l"(aa), "l"(ww))
#define BCAST2(aa, a) \
    asm("mov.b64 %0, {%1, %1};" : "=l"(aa) : "f"(a))

// ---------------------------------------------------------------------------
__global__ void k_deg(const int* __restrict__ ei, int E) {
    int i = blockIdx.x * blockDim.x + threadIdx.x;
    if (i < E) atomicAdd(&g_deg[ei[E + i]], 1);
}

// Single-pass decoupled-lookback exclusive scan of g_deg -> g_off,
// fused with cursor reset and dinv computation.
__global__ __launch_bounds__(512) void k_scan() {
    __shared__ int sh[512];
    __shared__ int s_prev;
    int t = threadIdx.x;
    int b = blockIdx.x;
    int i = b * 512 + t;
    int deg = (i < NN) ? g_deg[i] : 0;
    sh[t] = deg;
    for (int d = 1; d < 512; d <<= 1) {
        __syncthreads();
        int u = (t >= d) ? sh[t - d] : 0;
        __syncthreads();
        sh[t] += u;
    }
    __syncthreads();
    int agg = sh[511];

    if (t == 0) {
        if (b == 0) atomicExch(&g_lb[0], (2ULL << 32) | (unsigned)agg);
        else        atomicExch(&g_lb[b], (1ULL << 32) | (unsigned)agg);
    }

    if (b > 0 && t < 32) {                 // warp-parallel lookback
        int excl = 0;
        int hi = b - 1;
        for (;;) {
            int idx = hi - t;
            unsigned long long w = 0;
            if (idx >= 0) w = *(volatile unsigned long long*)&g_lb[idx];
            unsigned f = (idx >= 0) ? (unsigned)(w >> 32) : 2u;
            if (__ballot_sync(0xffffffffu, f == 0u)) continue;   // retry window
            int v = (int)(unsigned)(w & 0xffffffffULL);
            unsigned haspfx = __ballot_sync(0xffffffffu, f == 2u && idx >= 0);
            if (haspfx) {
                int first = __ffs(haspfx) - 1;   // nearest lane with a prefix
                int contrib = (idx >= 0 && t <= first) ? v : 0;
                #pragma unroll
                for (int o = 16; o; o >>= 1) contrib += __shfl_down_sync(0xffffffffu, contrib, o);
                excl += __shfl_sync(0xffffffffu, contrib, 0);
                break;
            } else {
                int contrib = (idx >= 0) ? v : 0;
                #pragma unroll
                for (int o = 16; o; o >>= 1) contrib += __shfl_down_sync(0xffffffffu, contrib, o);
                excl += __shfl_sync(0xffffffffu, contrib, 0);
                hi -= 32;
            }
        }
        if (t == 0) {
            s_prev = excl;
            atomicExch(&g_lb[b], (2ULL << 32) | (unsigned)(excl + agg));
        }
    } else if (b == 0 && t == 0) {
        s_prev = 0;
    }
    __syncthreads();

    if (i < NN) {
        g_off[i] = s_prev + sh[t] - deg;   // exclusive
        g_cur[i] = 0;
        g_dinv[i] = rsqrtf((float)deg + 1.0f);   // +1 self-loop
    }
    if (b == NSCAN_BLK - 1 && t == 511) g_off[NN] = s_prev + sh[511];
}

// Scatter edges into destination-grouped order; also reset deg/lookback state
// so the next call (graph replay) starts from the module-load invariant.
__global__ void k_scatter(const int* __restrict__ ei, int E) {
    int e = blockIdx.x * blockDim.x + threadIdx.x;
    if (e >= E) return;
    int s = ei[e];
    int d = ei[E + e];
    float norm = g_dinv[s] * g_dinv[d];
    int pos = g_off[d] + atomicAdd(&g_cur[d], 1);
    g_edge[pos] = make_int2(s, __float_as_int(norm));
    if (e < NN) g_deg[e] = 0;
    if (e < NSCAN_BLK) g_lb[e] = 0ULL;
}

// ---------------------------------------------------------------------------
// GEMM1: h1[NN,64] = x[NN,128] @ W1[128,64].
// 64 rows/block, 256 threads, 4 rows x 4 cols per thread, FFMA2 math,
// K chunked by 4 with float4 activation loads (fewer LDS wavefronts).
__global__ __launch_bounds__(256) void k_gemm1(const float* __restrict__ x,
                                               const float* __restrict__ W) {
    __shared__ float Ws[F1 * FH];   // 32 KB  [k][col]
    __shared__ float xs[64 * F1];   // 32 KB  [r][k]
    int tid = threadIdx.x;
    float4* Ws4 = (float4*)Ws;
    const float4* W4 = (const float4*)W;
    for (int i = tid; i < F1 * FH / 4; i += 256) Ws4[i] = W4[i];
    int row0 = blockIdx.x * 64;
    const float4* x4 = (const float4*)x;
    float4* xs4 = (float4*)xs;
    for (int i = tid; i < 64 * F1 / 4; i += 256) {
        int row = row0 + (i >> 5);                 // 32 float4 per row
        xs4[i] = (row < NN) ? x4[(size_t)row * 32 + (i & 31)]
                            : make_float4(0.f, 0.f, 0.f, 0.f);
    }
    __syncthreads();

    int tx = tid & 15;              // cols 4tx..4tx+3
    int ty = tid >> 4;              // rows 4ty..4ty+3
    const float* xr = xs + 4 * ty * F1;
    const ulonglong2* Wp = (const ulonglong2*)Ws;  // 16 per k-row (64 cols)
    unsigned long long acc[4][2] = {};             // 0 bits == {0.f, 0.f}

    #define G1_STEP(KK, CMP)                                               \
        do {                                                               \
            ulonglong2 w = Wp[(k + KK) * 16 + tx];                         \
            unsigned long long aa;                                         \
            BCAST2(aa, a0.CMP); FMA2(acc[0][0], aa, w.x); FMA2(acc[0][1], aa, w.y); \
            BCAST2(aa, a1.CMP); FMA2(acc[1][0], aa, w.x); FMA2(acc[1][1], aa, w.y); \
            BCAST2(aa, a2.CMP); FMA2(acc[2][0], aa, w.x); FMA2(acc[2][1], aa, w.y); \
            BCAST2(aa, a3.CMP); FMA2(acc[3][0], aa, w.x); FMA2(acc[3][1], aa, w.y); \
        } while (0)

    #pragma unroll 4
    for (int k = 0; k < F1; k += 4) {
        float4 a0 = *(const float4*)(xr + 0 * F1 + k);
        float4 a1 = *(const float4*)(xr + 1 * F1 + k);
        float4 a2 = *(const float4*)(xr + 2 * F1 + k);
        float4 a3 = *(const float4*)(xr + 3 * F1 + k);
        G1_STEP(0, x); G1_STEP(1, y); G1_STEP(2, z); G1_STEP(3, w);
    }
    #undef G1_STEP

    ulonglong2* h1v = (ulonglong2*)g_h1;           // 16 per row
    #pragma unroll
    for (int j = 0; j < 4; j++) {
        int row = row0 + 4 * ty + j;
        if (row < NN) h1v[(size_t)row * 16 + tx] = make_ulonglong2(acc[j][0], acc[j][1]);
    }
}

// Aggregation layer 1 (+ self-loop + bias + ReLU): 16 lanes per dst node,
// one float4 per lane per edge (LDG.128 gathers).
__global__ __launch_bounds__(256) void k_agg1(const float* __restrict__ b1) {
    int gid = blockIdx.x * 256 + threadIdx.x;
    int node = gid >> 4;
    int lane = threadIdx.x & 15;
    if (node >= NN) return;
    int off = g_off[node];
    int n   = g_off[node + 1] - off;
    const float4* h1v = (const float4*)g_h1;   // 16 float4 per row
    float4 acc = make_float4(0.f, 0.f, 0.f, 0.f);
    int i = 0;
    for (; i + 1 < n; i += 2) {
        int2 e0 = g_edge[off + i];
        int2 e1 = g_edge[off + i + 1];
        float4 p = h1v[(size_t)e0.x * 16 + lane];
        float4 q = h1v[(size_t)e1.x * 16 + lane];
        float n0 = __int_as_float(e0.y), n1 = __int_as_float(e1.y);
        acc.x = fmaf(p.x, n0, acc.x); acc.y = fmaf(p.y, n0, acc.y);
        acc.z = fmaf(p.z, n0, acc.z); acc.w = fmaf(p.w, n0, acc.w);
        acc.x = fmaf(q.x, n1, acc.x); acc.y = fmaf(q.y, n1, acc.y);
        acc.z = fmaf(q.z, n1, acc.z); acc.w = fmaf(q.w, n1, acc.w);
    }
    if (i < n) {
        int2 e0 = g_edge[off + i];
        float4 p = h1v[(size_t)e0.x * 16 + lane];
        float n0 = __int_as_float(e0.y);
        acc.x = fmaf(p.x, n0, acc.x); acc.y = fmaf(p.y, n0, acc.y);
        acc.z = fmaf(p.z, n0, acc.z); acc.w = fmaf(p.w, n0, acc.w);
    }
    float di = g_dinv[node], w = di * di;
    float4 hs = h1v[(size_t)node * 16 + lane];
    float4 bb = ((const float4*)b1)[lane];
    acc.x = fmaxf(fmaf(hs.x, w, acc.x) + bb.x, 0.f);
    acc.y = fmaxf(fmaf(hs.y, w, acc.y) + bb.y, 0.f);
    acc.z = fmaxf(fmaf(hs.z, w, acc.z) + bb.z, 0.f);
    acc.w = fmaxf(fmaf(hs.w, w, acc.w) + bb.w, 0.f);
    ((float4*)g_a1)[(size_t)node * 16 + lane] = acc;
}

// ---------------------------------------------------------------------------
// GEMM2: h3[NN,32] = a1[NN,64] @ W2[64,32].
// 128 rows/block, 256 threads, 4 rows x 4 cols per thread, FFMA2 math,
// K chunked by 4 with float4 activation loads.
__global__ __launch_bounds__(256) void k_gemm2(const float* __restrict__ W) {
    __shared__ float Ws[FH * FO];    // 8 KB
    __shared__ float xs[128 * FH];   // 32 KB
    int tid = threadIdx.x;
    float4* Ws4 = (float4*)Ws;
    const float4* W4 = (const float4*)W;
    for (int i = tid; i < FH * FO / 4; i += 256) Ws4[i] = W4[i];
    int row0 = blockIdx.x * 128;
    const float4* x4 = (const float4*)g_a1;
    float4* xs4 = (float4*)xs;
    for (int i = tid; i < 128 * FH / 4; i += 256) {
        int row = row0 + (i >> 4);                 // 16 float4 per row
        xs4[i] = (row < NN) ? x4[(size_t)row * 16 + (i & 15)]
                            : make_float4(0.f, 0.f, 0.f, 0.f);
    }
    __syncthreads();

    int tx = tid & 7;               // cols 4tx..4tx+3
    int ty = tid >> 3;              // rows 4ty..4ty+3
    const float* xr = xs + 4 * ty * FH;
    const ulonglong2* Wp = (const ulonglong2*)Ws;  // 8 per k-row (32 cols)
    unsigned long long acc[4][2] = {};

    #define G2_STEP(KK, CMP)                                               \
        do {                                                               \
            ulonglong2 w = Wp[(k + KK) * 8 + tx];                          \
            unsigned long long aa;                                         \
            BCAST2(aa, a0.CMP); FMA2(acc[0][0], aa, w.x); FMA2(acc[0][1], aa, w.y); \
            BCAST2(aa, a1.CMP); FMA2(acc[1][0], aa, w.x); FMA2(acc[1][1], aa, w.y); \
            BCAST2(aa, a2.CMP); FMA2(acc[2][0], aa, w.x); FMA2(acc[2][1], aa, w.y); \
            BCAST2(aa, a3.CMP); FMA2(acc[3][0], aa, w.x); FMA2(acc[3][1], aa, w.y); \
        } while (0)

    #pragma unroll 4
    for (int k = 0; k < FH; k += 4) {
        float4 a0 = *(const float4*)(xr + 0 * FH + k);
        float4 a1 = *(const float4*)(xr + 1 * FH + k);
        float4 a2 = *(const float4*)(xr + 2 * FH + k);
        float4 a3 = *(const float4*)(xr + 3 * FH + k);
        G2_STEP(0, x); G2_STEP(1, y); G2_STEP(2, z); G2_STEP(3, w);
    }
    #undef G2_STEP

    ulonglong2* h3v = (ulonglong2*)g_h3;           // 8 per row
    #pragma unroll
    for (int j = 0; j < 4; j++) {
        int row = row0 + 4 * ty + j;
        if (row < NN) h3v[(size_t)row * 8 + tx] = make_ulonglong2(acc[j][0], acc[j][1]);
    }
}

// Aggregation layer 2 (+ self-loop + bias): 8 lanes per dst node, float4 per
// lane per edge, plain store into d_out.
__global__ __launch_bounds__(256) void k_agg2(float* __restrict__ out,
                                              const float* __restrict__ b2) {
    int gid = blockIdx.x * 256 + threadIdx.x;
    int node = gid >> 3;
    int lane = threadIdx.x & 7;
    if (node >= NN) return;
    int off = g_off[node];
    int n   = g_off[node + 1] - off;
    const float4* h3v = (const float4*)g_h3;   // 8 float4 per row
    float4 acc = make_float4(0.f, 0.f, 0.f, 0.f);
    int i = 0;
    for (; i + 1 < n; i += 2) {
        int2 e0 = g_edge[off + i];
        int2 e1 = g_edge[off + i + 1];
        float4 p = h3v[(size_t)e0.x * 8 + lane];
        float4 q = h3v[(size_t)e1.x * 8 + lane];
        float n0 = __int_as_float(e0.y), n1 = __int_as_float(e1.y);
        acc.x = fmaf(p.x, n0, acc.x); acc.y = fmaf(p.y, n0, acc.y);
        acc.z = fmaf(p.z, n0, acc.z); acc.w = fmaf(p.w, n0, acc.w);
        acc.x = fmaf(q.x, n1, acc.x); acc.y = fmaf(q.y, n1, acc.y);
        acc.z = fmaf(q.z, n1, acc.z); acc.w = fmaf(q.w, n1, acc.w);
    }
    if (i < n) {
        int2 e0 = g_edge[off + i];
        float4 p = h3v[(size_t)e0.x * 8 + lane];
        float n0 = __int_as_float(e0.y);
        acc.x = fmaf(p.x, n0, acc.x); acc.y = fmaf(p.y, n0, acc.y);
        acc.z = fmaf(p.z, n0, acc.z); acc.w = fmaf(p.w, n0, acc.w);
    }
    float di = g_dinv[node], w = di * di;
    float4 hs = h3v[(size_t)node * 8 + lane];
    float4 bb = ((const float4*)b2)[lane];
    acc.x = fmaf(hs.x, w, acc.x) + bb.x;
    acc.y = fmaf(hs.y, w, acc.y) + bb.y;
    acc.z = fmaf(hs.z, w, acc.z) + bb.z;
    acc.w = fmaf(hs.w, w, acc.w) + bb.w;
    ((float4*)out)[(size_t)node * 8 + lane] = acc;
}

// ---------------------------------------------------------------------------
namespace {
struct Ctx {
    cudaStream_t s2;
    cudaEvent_t e_fork, e_join;
    Ctx() {
        cudaStreamCreateWithFlags(&s2, cudaStreamNonBlocking);
        cudaEventCreateWithFlags(&e_fork, cudaEventDisableTiming);
        cudaEventCreateWithFlags(&e_join, cudaEventDisableTiming);
    }
};
}

extern "C" void kernel_launch(void* const* d_in, const int* in_sizes, int n_in,
                              void* d_out, int out_size) {
    static Ctx ctx;   // created on first (uncaptured) correctness call

    const float* x  = (const float*)d_in[0];
    const int*   ei = (const int*)d_in[1];     // int32 (JAX x64 disabled)
    const float* W1 = (const float*)d_in[2];
    const float* b1 = (const float*)d_in[3];
    const float* W2 = (const float*)d_in[4];
    const float* b2 = (const float*)d_in[5];
    float* out = (float*)d_out;

    const int E = in_sizes[1] / 2;

    // Fork: graph preprocessing on ctx.s2 concurrently with GEMM1 (disjoint
    // resources: L2-atomic/DRAM vs LDS/FMA).
    cudaEventRecord(ctx.e_fork, 0);
    cudaStreamWaitEvent(ctx.s2, ctx.e_fork, 0);

    k_deg<<<(E + 255) / 256, 256, 0, ctx.s2>>>(ei, E);
    k_scan<<<NSCAN_BLK, 512, 0, ctx.s2>>>();
    k_scatter<<<(E + 255) / 256, 256, 0, ctx.s2>>>(ei, E);
    cudaEventRecord(ctx.e_join, ctx.s2);

    k_gemm1<<<(NN + 63) / 64, 256>>>(x, W1);

    // Join: aggregation needs both h1 and the grouped edge list.
    cudaStreamWaitEvent(0, ctx.e_join, 0);

    k_agg1<<<(NN * 16 + 255) / 256, 256>>>(b1);
    k_gemm2<<<(NN + 127) / 128, 256>>>(W2);
    k_agg2<<<(NN * 8 + 255) / 256, 256>>>(out, b2);
}